// round 1
// baseline (speedup 1.0000x reference)
#include <cuda_runtime.h>
#include <math.h>

#define Bn 4
#define Pp 4
#define Cc 64
#define NH 8
#define DH 8
#define Hh 128
#define Wd 128
#define HW 16384
#define TOK 32

// scratch (no cudaMalloc allowed)
__device__ float g_mb[16 * HW];     // [(b*4+p)][pos] mask-bias per polarization
__device__ float g_wbar[Cc + 1];    // column-mean of pw_w + mean(pw_b)

// ---------------------------------------------------------------------------
// Kernel 0: fold pointwise conv + channel-mean into a 64-vector.
// mean_d( pw_w[d][c]*g[c] + pw_b[d] ) = (mean_d pw_w[d][c]) . g  + mean(pw_b)
// ---------------------------------------------------------------------------
__global__ void wbar_kernel(const float* __restrict__ pw_w,
                            const float* __restrict__ pw_b) {
    int c = threadIdx.x;
    float s = 0.f;
    for (int d = 0; d < Cc; ++d) s += pw_w[d * Cc + c];
    g_wbar[c] = s * (1.0f / Cc);
    if (c == 0) {
        float sb = 0.f;
        for (int d = 0; d < Cc; ++d) sb += pw_b[d];
        g_wbar[Cc] = sb * (1.0f / Cc);
    }
}

// ---------------------------------------------------------------------------
// Kernel 1: mask branch. depthwise 3x3 (SAME, zero pad) -> exact GELU ->
// dot with g_wbar -> g_mb[bp][pos]
// ---------------------------------------------------------------------------
__global__ void mask_kernel(const float* __restrict__ mask) {
    __shared__ float tile[18][20];
    __shared__ float sdw[Cc][9];
    __shared__ float sdb[Cc];
    __shared__ float swbar[Cc + 1];

    int bp = blockIdx.z;
    int h0 = blockIdx.y * 16, w0 = blockIdx.x * 16;
    int tx = threadIdx.x, ty = threadIdx.y;
    int tid = ty * 16 + tx;

    // dw weights staged via constant-ish path: passed through smem
    // (loaded from global below, using pointers stashed in g_dw via launch args)
    // -> we instead receive them through __restrict__ globals (see launch)
    extern __shared__ float dummy[]; (void)dummy;

    // dw_w / dw_b come in via the global pointers set below
    // (loaded inside kernel via parameters in mask_kernel2)
    (void)mask; (void)bp; (void)h0; (void)w0; (void)tid; (void)sdw; (void)sdb; (void)swbar; (void)tile;
}

// real mask kernel (with all params)
__global__ void mask_kernel2(const float* __restrict__ mask,
                             const float* __restrict__ dw_w,
                             const float* __restrict__ dw_b) {
    __shared__ float tile[18][20];
    __shared__ float sdw[Cc][9];
    __shared__ float sdb[Cc];
    __shared__ float swbar[Cc + 1];

    int bp = blockIdx.z;
    int h0 = blockIdx.y * 16, w0 = blockIdx.x * 16;
    int tx = threadIdx.x, ty = threadIdx.y;
    int tid = ty * 16 + tx;

    for (int i = tid; i < Cc * 9; i += 256) sdw[i / 9][i % 9] = dw_w[i];
    for (int i = tid; i < Cc; i += 256) { sdb[i] = dw_b[i]; swbar[i] = g_wbar[i]; }
    if (tid == 0) swbar[Cc] = g_wbar[Cc];

    float acc = 0.f;
    const float* base = mask + (size_t)bp * Cc * HW;

    for (int c = 0; c < Cc; ++c) {
        __syncthreads();  // also covers the init loads on first iter
        for (int i = tid; i < 18 * 18; i += 256) {
            int hy = i / 18, wx = i % 18;
            int gh = h0 + hy - 1, gw = w0 + wx - 1;
            float v = 0.f;
            if (gh >= 0 && gh < Hh && gw >= 0 && gw < Wd)
                v = base[(size_t)c * HW + gh * Wd + gw];
            tile[hy][wx] = v;
        }
        __syncthreads();
        float y = sdb[c];
#pragma unroll
        for (int dy = 0; dy < 3; ++dy)
#pragma unroll
            for (int dx = 0; dx < 3; ++dx)
                y += tile[ty + dy][tx + dx] * sdw[c][dy * 3 + dx];
        // exact GELU
        float g = 0.5f * y * (1.0f + erff(y * 0.70710678118654752f));
        acc += swbar[c] * g;
    }
    acc += swbar[Cc];
    g_mb[(size_t)bp * HW + (h0 + ty) * Wd + (w0 + tx)] = acc;
}

// ---------------------------------------------------------------------------
// Kernel 2: fused QKV + normalize + 4x4 cross-polar attention + softmax
//           + AV + output projection + coalesced writeback.
// block = 256 threads = 32 tokens x 8 heads; grid = (HW/32, B)
// smem (floats):
//   sW   [4][64][64]  0      (transposed: [c][d])  wq,wk,wv,wproj
//   o_s  [64][32][4]  16384
//   x_s  [64][32][4]  24576  (aliased as out_s [256][32] in proj phase)
//   mb_s [32][4]      32768
//   sb   [64]         32896
//   sr   [8]          32960
// total = 32968 floats = 131872 B
// ---------------------------------------------------------------------------
#define SMEM_FLOATS 32968

__global__ void attn_kernel(const float* __restrict__ x_in,
                            const float* __restrict__ wq,
                            const float* __restrict__ wk,
                            const float* __restrict__ wv,
                            const float* __restrict__ wp,
                            const float* __restrict__ b_proj,
                            const float* __restrict__ rescale,
                            float* __restrict__ out) {
    extern __shared__ float sm[];
    float* sW  = sm;
    float* o_s = sm + 16384;
    float* x_s = sm + 24576;   // aliased out_s
    float* mb_s = sm + 32768;
    float* sb  = sm + 32896;
    float* sr  = sm + 32960;

    int tid = threadIdx.x;
    int b = blockIdx.y;
    int pos0 = blockIdx.x * TOK;

    // --- stage weights transposed [c][d] (global read coalesced over c) ---
    const float* Ws[4] = {wq, wk, wv, wp};
#pragma unroll
    for (int m = 0; m < 4; ++m) {
        for (int idx = tid; idx < 4096; idx += 256) {
            int d = idx >> 6, c = idx & 63;
            sW[m * 4096 + c * 64 + d] = Ws[m][idx];
        }
    }
    // --- stage x as x_s[c][t][p] (global coalesced over pos) ---
    for (int idx = tid; idx < 8192; idx += 256) {
        int pc = idx >> 5;       // p*64 + c
        int t = idx & 31;
        int p = pc >> 6, c = pc & 63;
        x_s[c * 128 + t * 4 + p] =
            x_in[(size_t)((b * 4 + p) * 64 + c) * HW + pos0 + t];
    }
    if (tid < 128) {
        int p = tid >> 5, t = tid & 31;
        mb_s[t * 4 + p] = g_mb[(size_t)(b * 4 + p) * HW + pos0 + t];
    }
    if (tid < 64) sb[tid] = b_proj[tid];
    if (tid < 8) sr[tid] = rescale[tid];
    __syncthreads();

    const int t = tid >> 3;    // token in tile
    const int h = tid & 7;     // head

    float q[4][8], k[4][8], v[4][8];
#pragma unroll
    for (int p = 0; p < 4; ++p)
#pragma unroll
        for (int j = 0; j < 8; ++j) { q[p][j] = 0.f; k[p][j] = 0.f; v[p][j] = 0.f; }

    const float* wqb = sW + h * 8;
    const float* wkb = sW + 4096 + h * 8;
    const float* wvb = sW + 8192 + h * 8;

#pragma unroll 4
    for (int c = 0; c < 64; ++c) {
        float4 xv = *(const float4*)(x_s + c * 128 + t * 4);
        float xr[4] = {xv.x, xv.y, xv.z, xv.w};
        float4 q0 = *(const float4*)(wqb + c * 64);
        float4 q1 = *(const float4*)(wqb + c * 64 + 4);
        float4 k0 = *(const float4*)(wkb + c * 64);
        float4 k1 = *(const float4*)(wkb + c * 64 + 4);
        float4 v0 = *(const float4*)(wvb + c * 64);
        float4 v1 = *(const float4*)(wvb + c * 64 + 4);
        float wqr[8] = {q0.x, q0.y, q0.z, q0.w, q1.x, q1.y, q1.z, q1.w};
        float wkr[8] = {k0.x, k0.y, k0.z, k0.w, k1.x, k1.y, k1.z, k1.w};
        float wvr[8] = {v0.x, v0.y, v0.z, v0.w, v1.x, v1.y, v1.z, v1.w};
#pragma unroll
        for (int p = 0; p < 4; ++p) {
            float xp = xr[p];
#pragma unroll
            for (int j = 0; j < 8; ++j) {
                q[p][j] = fmaf(xp, wqr[j], q[p][j]);
                k[p][j] = fmaf(xp, wkr[j], k[p][j]);
                v[p][j] = fmaf(xp, wvr[j], v[p][j]);
            }
        }
    }

    // --- L2 normalize q,k per (p,h) over DH=8, clamp by eps ---
#pragma unroll
    for (int p = 0; p < 4; ++p) {
        float sq = 0.f, sk = 0.f;
#pragma unroll
        for (int j = 0; j < 8; ++j) { sq += q[p][j] * q[p][j]; sk += k[p][j] * k[p][j]; }
        float iq = 1.0f / fmaxf(sqrtf(sq), 1e-12f);
        float ik = 1.0f / fmaxf(sqrtf(sk), 1e-12f);
#pragma unroll
        for (int j = 0; j < 8; ++j) { q[p][j] *= iq; k[p][j] *= ik; }
    }

    float mbl[4];
#pragma unroll
    for (int p = 0; p < 4; ++p) mbl[p] = mb_s[t * 4 + p];
    float rh = sr[h];

    float att[4][4];
#pragma unroll
    for (int p = 0; p < 4; ++p) {
#pragma unroll
        for (int pq = 0; pq < 4; ++pq) {
            float d = 0.f;
#pragma unroll
            for (int j = 0; j < 8; ++j) d += q[p][j] * k[pq][j];
            att[p][pq] = d * rh + (mbl[pq] - mbl[p]);
        }
        // softmax over pq
        float mx = fmaxf(fmaxf(att[p][0], att[p][1]), fmaxf(att[p][2], att[p][3]));
        float s = 0.f;
#pragma unroll
        for (int pq = 0; pq < 4; ++pq) { att[p][pq] = __expf(att[p][pq] - mx); s += att[p][pq]; }
        float inv = 1.0f / s;
#pragma unroll
        for (int pq = 0; pq < 4; ++pq) att[p][pq] *= inv;
    }

    // --- o = att @ v ; stash to o_s[c][t][p] ---
#pragma unroll
    for (int p = 0; p < 4; ++p) {
#pragma unroll
        for (int j = 0; j < 8; ++j) {
            float o = att[p][0] * v[0][j] + att[p][1] * v[1][j] +
                      att[p][2] * v[2][j] + att[p][3] * v[3][j];
            o_s[(h * 8 + j) * 128 + t * 4 + p] = o;
        }
    }
    __syncthreads();

    // --- projection: out[p][h*8+j] = sum_c o[p][c] * wp[h*8+j][c] + b ---
    float acc[4][8];
#pragma unroll
    for (int p = 0; p < 4; ++p)
#pragma unroll
        for (int j = 0; j < 8; ++j) acc[p][j] = sb[h * 8 + j];

    const float* wpb = sW + 12288 + h * 8;
#pragma unroll 4
    for (int c = 0; c < 64; ++c) {
        float4 ov = *(const float4*)(o_s + c * 128 + t * 4);
        float orr[4] = {ov.x, ov.y, ov.z, ov.w};
        float4 w0 = *(const float4*)(wpb + c * 64);
        float4 w1 = *(const float4*)(wpb + c * 64 + 4);
        float wr[8] = {w0.x, w0.y, w0.z, w0.w, w1.x, w1.y, w1.z, w1.w};
#pragma unroll
        for (int p = 0; p < 4; ++p) {
            float op = orr[p];
#pragma unroll
            for (int j = 0; j < 8; ++j) acc[p][j] = fmaf(op, wr[j], acc[p][j]);
        }
    }

    // --- stage to out_s[(p*64+c)][t] (x_s region, x dead) ---
#pragma unroll
    for (int p = 0; p < 4; ++p)
#pragma unroll
        for (int j = 0; j < 8; ++j)
            x_s[(p * 64 + h * 8 + j) * 32 + t] = acc[p][j];
    __syncthreads();

    // --- coalesced writeback ---
    for (int idx = tid; idx < 8192; idx += 256) {
        int pc = idx >> 5;
        int tt = idx & 31;
        int p = pc >> 6, c = pc & 63;
        out[(size_t)((b * 4 + p) * 64 + c) * HW + pos0 + tt] = x_s[pc * 32 + tt];
    }
}

// ---------------------------------------------------------------------------
extern "C" void kernel_launch(void* const* d_in, const int* in_sizes, int n_in,
                              void* d_out, int out_size) {
    (void)in_sizes; (void)n_in; (void)out_size;
    const float* x_in   = (const float*)d_in[0];
    const float* mask   = (const float*)d_in[1];
    const float* wq     = (const float*)d_in[2];
    const float* wk     = (const float*)d_in[3];
    const float* wv     = (const float*)d_in[4];
    const float* w_proj = (const float*)d_in[5];
    const float* b_proj = (const float*)d_in[6];
    const float* rescale= (const float*)d_in[7];
    const float* dw_w   = (const float*)d_in[8];
    const float* dw_b   = (const float*)d_in[9];
    const float* pw_w   = (const float*)d_in[10];
    const float* pw_b   = (const float*)d_in[11];
    float* out = (float*)d_out;

    cudaFuncSetAttribute(attn_kernel,
                         cudaFuncAttributeMaxDynamicSharedMemorySize,
                         SMEM_FLOATS * sizeof(float));

    wbar_kernel<<<1, 64>>>(pw_w, pw_b);
    mask_kernel2<<<dim3(8, 8, 16), dim3(16, 16)>>>(mask, dw_w, dw_b);
    attn_kernel<<<dim3(HW / TOK, Bn), 256, SMEM_FLOATS * sizeof(float)>>>(
        x_in, wq, wk, wv, w_proj, b_proj, rescale, out);
}

// round 2
// speedup vs baseline: 1.1335x; 1.1335x over previous
#include <cuda_runtime.h>
#include <math.h>

#define Bn 4
#define Pp 4
#define Cc 64
#define NH 8
#define DH 8
#define Hh 128
#define Wd 128
#define HW 16384
#define TOK 32

// scratch (no cudaMalloc allowed)
__device__ float g_mb[16 * HW];     // [(b*4+p)][pos] mask-bias per polarization
__device__ float g_wbar[Cc + 1];    // column-mean of pw_w + mean(pw_b)

// ---------------------------------------------------------------------------
// packed f32x2 helpers (SASS FFMA2 path — ptxas won't emit this from C++)
// ---------------------------------------------------------------------------
__device__ __forceinline__ unsigned long long fma2(unsigned long long a,
                                                   unsigned long long b,
                                                   unsigned long long c) {
    unsigned long long d;
    asm("fma.rn.f32x2 %0, %1, %2, %3;" : "=l"(d) : "l"(a), "l"(b), "l"(c));
    return d;
}
__device__ __forceinline__ unsigned long long pack2(float lo, float hi) {
    unsigned long long d;
    asm("mov.b64 %0, {%1, %2};" : "=l"(d) : "f"(lo), "f"(hi));
    return d;
}
__device__ __forceinline__ void unpack2(unsigned long long v, float& lo, float& hi) {
    asm("mov.b64 {%0, %1}, %2;" : "=f"(lo), "=f"(hi) : "l"(v));
}

// ---------------------------------------------------------------------------
// Kernel 0: fold pointwise conv + channel-mean into a 64-vector.
// ---------------------------------------------------------------------------
__global__ void wbar_kernel(const float* __restrict__ pw_w,
                            const float* __restrict__ pw_b) {
    int c = threadIdx.x;
    float s = 0.f;
    for (int d = 0; d < Cc; ++d) s += pw_w[d * Cc + c];
    g_wbar[c] = s * (1.0f / Cc);
    if (c == 0) {
        float sb = 0.f;
        for (int d = 0; d < Cc; ++d) sb += pw_b[d];
        g_wbar[Cc] = sb * (1.0f / Cc);
    }
}

// ---------------------------------------------------------------------------
// Kernel 1: mask branch. depthwise 3x3 (SAME) -> exact GELU -> dot wbar
// ---------------------------------------------------------------------------
__global__ void mask_kernel2(const float* __restrict__ mask,
                             const float* __restrict__ dw_w,
                             const float* __restrict__ dw_b) {
    __shared__ float tile[18][20];
    __shared__ float sdw[Cc][9];
    __shared__ float sdb[Cc];
    __shared__ float swbar[Cc + 1];

    int bp = blockIdx.z;
    int h0 = blockIdx.y * 16, w0 = blockIdx.x * 16;
    int tx = threadIdx.x, ty = threadIdx.y;
    int tid = ty * 16 + tx;

    for (int i = tid; i < Cc * 9; i += 256) sdw[i / 9][i % 9] = dw_w[i];
    for (int i = tid; i < Cc; i += 256) { sdb[i] = dw_b[i]; swbar[i] = g_wbar[i]; }
    if (tid == 0) swbar[Cc] = g_wbar[Cc];

    float acc = 0.f;
    const float* base = mask + (size_t)bp * Cc * HW;

    for (int c = 0; c < Cc; ++c) {
        __syncthreads();
        for (int i = tid; i < 18 * 18; i += 256) {
            int hy = i / 18, wx = i % 18;
            int gh = h0 + hy - 1, gw = w0 + wx - 1;
            float v = 0.f;
            if (gh >= 0 && gh < Hh && gw >= 0 && gw < Wd)
                v = base[(size_t)c * HW + gh * Wd + gw];
            tile[hy][wx] = v;
        }
        __syncthreads();
        float y = sdb[c];
#pragma unroll
        for (int dy = 0; dy < 3; ++dy)
#pragma unroll
            for (int dx = 0; dx < 3; ++dx)
                y += tile[ty + dy][tx + dx] * sdw[c][dy * 3 + dx];
        float g = 0.5f * y * (1.0f + erff(y * 0.70710678118654752f));
        acc += swbar[c] * g;
    }
    acc += swbar[Cc];
    g_mb[(size_t)bp * HW + (h0 + ty) * Wd + (w0 + tx)] = acc;
}

// ---------------------------------------------------------------------------
// Kernel 2: fused QK + normalize + 4x4 softmax + algebraically-fused AV
//           (o = (att-mixed x) @ Wv) + projection, all in f32x2 packed FMA.
// block = 256 threads = 32 tokens x 8 heads; 2 blocks/SM.
// smem (floats):
//   sW   [4][64][64]  0        (transposed [c][d])  wq,wk,wv,wproj
//   x_s  [64][32][4]  16384    (aliased: o_s, then out staging [256][32])
//   mb_s [32][4]      24576
//   sb   [64]         24704
//   sr   [8]          24768
// total = 24776 floats = 99104 B  -> 2 blocks/SM
// ---------------------------------------------------------------------------
#define SMEM_FLOATS 24776

__global__ void __launch_bounds__(256, 2)
attn_kernel(const float* __restrict__ x_in,
            const float* __restrict__ wq,
            const float* __restrict__ wk,
            const float* __restrict__ wv,
            const float* __restrict__ wp,
            const float* __restrict__ b_proj,
            const float* __restrict__ rescale,
            float* __restrict__ out) {
    extern __shared__ float sm[];
    float* sW   = sm;
    float* x_s  = sm + 16384;   // aliased o_s / out_s
    float* mb_s = sm + 24576;
    float* sb   = sm + 24704;
    float* sr   = sm + 24768;

    int tid = threadIdx.x;
    int b = blockIdx.y;
    int pos0 = blockIdx.x * TOK;

    // --- stage weights transposed [c][d] ---
    const float* Ws[4] = {wq, wk, wv, wp};
#pragma unroll
    for (int m = 0; m < 4; ++m) {
        for (int idx = tid; idx < 4096; idx += 256) {
            int d = idx >> 6, c = idx & 63;
            sW[m * 4096 + c * 64 + d] = Ws[m][idx];
        }
    }
    // --- stage x as x_s[c][t][p] ---
    for (int idx = tid; idx < 8192; idx += 256) {
        int pc = idx >> 5;
        int t = idx & 31;
        int p = pc >> 6, c = pc & 63;
        x_s[c * 128 + t * 4 + p] =
            x_in[(size_t)((b * 4 + p) * 64 + c) * HW + pos0 + t];
    }
    if (tid < 128) {
        int p = tid >> 5, t = tid & 31;
        mb_s[t * 4 + p] = g_mb[(size_t)(b * 4 + p) * HW + pos0 + t];
    }
    if (tid < 64) sb[tid] = b_proj[tid];
    if (tid < 8) sr[tid] = rescale[tid];
    __syncthreads();

    const int t = tid >> 3;    // token in tile
    const int h = tid & 7;     // head

    const float* wqb = sW + h * 8;
    const float* wkb = sW + 4096 + h * 8;
    const float* wvb = sW + 8192 + h * 8;
    const float* wpb = sW + 12288 + h * 8;

    // ===== phase 1: Q,K GEMM (packed over j-pairs) =====
    unsigned long long qa[4][4], ka[4][4];
#pragma unroll
    for (int p = 0; p < 4; ++p)
#pragma unroll
        for (int i = 0; i < 4; ++i) { qa[p][i] = 0ULL; ka[p][i] = 0ULL; }

#pragma unroll 2
    for (int c = 0; c < 64; ++c) {
        float4 xv = *(const float4*)(x_s + c * 128 + t * 4);
        ulonglong2 wq0 = *(const ulonglong2*)(wqb + c * 64);
        ulonglong2 wq1 = *(const ulonglong2*)(wqb + c * 64 + 4);
        ulonglong2 wk0 = *(const ulonglong2*)(wkb + c * 64);
        ulonglong2 wk1 = *(const ulonglong2*)(wkb + c * 64 + 4);
        float xr[4] = {xv.x, xv.y, xv.z, xv.w};
#pragma unroll
        for (int p = 0; p < 4; ++p) {
            unsigned long long xp2 = pack2(xr[p], xr[p]);
            qa[p][0] = fma2(xp2, wq0.x, qa[p][0]);
            qa[p][1] = fma2(xp2, wq0.y, qa[p][1]);
            qa[p][2] = fma2(xp2, wq1.x, qa[p][2]);
            qa[p][3] = fma2(xp2, wq1.y, qa[p][3]);
            ka[p][0] = fma2(xp2, wk0.x, ka[p][0]);
            ka[p][1] = fma2(xp2, wk0.y, ka[p][1]);
            ka[p][2] = fma2(xp2, wk1.x, ka[p][2]);
            ka[p][3] = fma2(xp2, wk1.y, ka[p][3]);
        }
    }

    // unpack
    float q[4][8], k[4][8];
#pragma unroll
    for (int p = 0; p < 4; ++p)
#pragma unroll
        for (int i = 0; i < 4; ++i) {
            unpack2(qa[p][i], q[p][2 * i], q[p][2 * i + 1]);
            unpack2(ka[p][i], k[p][2 * i], k[p][2 * i + 1]);
        }

    // ===== L2 normalize =====
#pragma unroll
    for (int p = 0; p < 4; ++p) {
        float sq = 0.f, sk = 0.f;
#pragma unroll
        for (int j = 0; j < 8; ++j) { sq += q[p][j] * q[p][j]; sk += k[p][j] * k[p][j]; }
        float iq = 1.0f / fmaxf(sqrtf(sq), 1e-12f);
        float ik = 1.0f / fmaxf(sqrtf(sk), 1e-12f);
#pragma unroll
        for (int j = 0; j < 8; ++j) { q[p][j] *= iq; k[p][j] *= ik; }
    }

    float mbl[4];
#pragma unroll
    for (int p = 0; p < 4; ++p) mbl[p] = mb_s[t * 4 + p];
    float rh = sr[h];

    // ===== attention scores + softmax =====
    float att[4][4];
#pragma unroll
    for (int p = 0; p < 4; ++p) {
#pragma unroll
        for (int pq = 0; pq < 4; ++pq) {
            float d = 0.f;
#pragma unroll
            for (int j = 0; j < 8; ++j) d += q[p][j] * k[pq][j];
            att[p][pq] = d * rh + (mbl[pq] - mbl[p]);
        }
        float mx = fmaxf(fmaxf(att[p][0], att[p][1]), fmaxf(att[p][2], att[p][3]));
        float s = 0.f;
#pragma unroll
        for (int pq = 0; pq < 4; ++pq) { att[p][pq] = __expf(att[p][pq] - mx); s += att[p][pq]; }
        float inv = 1.0f / s;
#pragma unroll
        for (int pq = 0; pq < 4; ++pq) att[p][pq] *= inv;
    }

    // ===== phase 2: fused AV:  o[p][j] = sum_c ( sum_pq att[p][pq] x[pq][c] ) * wv[c][j]
    unsigned long long oa[4][4];
#pragma unroll
    for (int p = 0; p < 4; ++p)
#pragma unroll
        for (int i = 0; i < 4; ++i) oa[p][i] = 0ULL;

#pragma unroll 2
    for (int c = 0; c < 64; ++c) {
        float4 xv = *(const float4*)(x_s + c * 128 + t * 4);
        ulonglong2 wv0 = *(const ulonglong2*)(wvb + c * 64);
        ulonglong2 wv1 = *(const ulonglong2*)(wvb + c * 64 + 4);
#pragma unroll
        for (int p = 0; p < 4; ++p) {
            float y = att[p][0] * xv.x + att[p][1] * xv.y +
                      att[p][2] * xv.z + att[p][3] * xv.w;
            unsigned long long y2 = pack2(y, y);
            oa[p][0] = fma2(y2, wv0.x, oa[p][0]);
            oa[p][1] = fma2(y2, wv0.y, oa[p][1]);
            oa[p][2] = fma2(y2, wv1.x, oa[p][2]);
            oa[p][3] = fma2(y2, wv1.y, oa[p][3]);
        }
    }

    // x_s becomes o_s — wait for all readers of x_s first
    __syncthreads();
#pragma unroll
    for (int p = 0; p < 4; ++p)
#pragma unroll
        for (int i = 0; i < 4; ++i) {
            float lo, hi;
            unpack2(oa[p][i], lo, hi);
            x_s[(h * 8 + 2 * i) * 128 + t * 4 + p] = lo;
            x_s[(h * 8 + 2 * i + 1) * 128 + t * 4 + p] = hi;
        }
    __syncthreads();

    // ===== phase 3: projection (packed) =====
    unsigned long long acc[4][4];
    {
        ulonglong2 b0 = *(const ulonglong2*)(sb + h * 8);
        ulonglong2 b1 = *(const ulonglong2*)(sb + h * 8 + 4);
#pragma unroll
        for (int p = 0; p < 4; ++p) {
            acc[p][0] = b0.x; acc[p][1] = b0.y; acc[p][2] = b1.x; acc[p][3] = b1.y;
        }
    }
#pragma unroll 2
    for (int c = 0; c < 64; ++c) {
        float4 ov = *(const float4*)(x_s + c * 128 + t * 4);
        ulonglong2 w0 = *(const ulonglong2*)(wpb + c * 64);
        ulonglong2 w1 = *(const ulonglong2*)(wpb + c * 64 + 4);
        float orr[4] = {ov.x, ov.y, ov.z, ov.w};
#pragma unroll
        for (int p = 0; p < 4; ++p) {
            unsigned long long o2 = pack2(orr[p], orr[p]);
            acc[p][0] = fma2(o2, w0.x, acc[p][0]);
            acc[p][1] = fma2(o2, w0.y, acc[p][1]);
            acc[p][2] = fma2(o2, w1.x, acc[p][2]);
            acc[p][3] = fma2(o2, w1.y, acc[p][3]);
        }
    }

    // stage to out_s[(p*64+c)][t] (x_s region, o dead after proj loop)
    __syncthreads();
#pragma unroll
    for (int p = 0; p < 4; ++p)
#pragma unroll
        for (int i = 0; i < 4; ++i) {
            float lo, hi;
            unpack2(acc[p][i], lo, hi);
            x_s[(p * 64 + h * 8 + 2 * i) * 32 + t] = lo;
            x_s[(p * 64 + h * 8 + 2 * i + 1) * 32 + t] = hi;
        }
    __syncthreads();

    // coalesced writeback
    for (int idx = tid; idx < 8192; idx += 256) {
        int pc = idx >> 5;
        int tt = idx & 31;
        int p = pc >> 6, c = pc & 63;
        out[(size_t)((b * 4 + p) * 64 + c) * HW + pos0 + tt] = x_s[pc * 32 + tt];
    }
}

// ---------------------------------------------------------------------------
extern "C" void kernel_launch(void* const* d_in, const int* in_sizes, int n_in,
                              void* d_out, int out_size) {
    (void)in_sizes; (void)n_in; (void)out_size;
    const float* x_in   = (const float*)d_in[0];
    const float* mask   = (const float*)d_in[1];
    const float* wq     = (const float*)d_in[2];
    const float* wk     = (const float*)d_in[3];
    const float* wv     = (const float*)d_in[4];
    const float* w_proj = (const float*)d_in[5];
    const float* b_proj = (const float*)d_in[6];
    const float* rescale= (const float*)d_in[7];
    const float* dw_w   = (const float*)d_in[8];
    const float* dw_b   = (const float*)d_in[9];
    const float* pw_w   = (const float*)d_in[10];
    const float* pw_b   = (const float*)d_in[11];
    float* out = (float*)d_out;

    cudaFuncSetAttribute(attn_kernel,
                         cudaFuncAttributeMaxDynamicSharedMemorySize,
                         SMEM_FLOATS * sizeof(float));

    wbar_kernel<<<1, 64>>>(pw_w, pw_b);
    mask_kernel2<<<dim3(8, 8, 16), dim3(16, 16)>>>(mask, dw_w, dw_b);
    attn_kernel<<<dim3(HW / TOK, Bn), 256, SMEM_FLOATS * sizeof(float)>>>(
        x_in, wq, wk, wv, w_proj, b_proj, rescale, out);
}